// round 15
// baseline (speedup 1.0000x reference)
#include <cuda_runtime.h>
#include <math.h>
#include <stdint.h>

#define NPTS    8192
#define NB      2
#define TNN     128                        // threads per NN block
#define QPT     4                          // queries per thread
#define QCHUNK  (TNN * QPT)                // 512 queries per block
#define SEG     256                        // candidate segment (occupancy!)
#define GRP     8                          // tracking-group size (2 quads)
#define NSEG    (NPTS / SEG)               // 32
#define NQCHUNK (NPTS / QCHUNK)            // 16
#define NQ_TOTAL (2 * NB * NPTS)           // 32768
#define NN_BLOCKS (2 * NB * NQCHUNK * NSEG)   // 2048
#define TLOSS   256
#define LOSS_BLOCKS (NQ_TOTAL / TLOSS)        // 128

// Scratch. g_segkeys[seg][global_q]: per-segment winner, plain stores (every
// slot rewritten each replay -> no init needed). Key packs
// (order-preserving score bits << 32 | candidate idx): u64 min == (min score,
// lowest idx), matching the reference argmin tie-break.
__device__ unsigned long long g_segkeys[NSEG * NQ_TOTAL];
__device__ unsigned long long g_keys[NQ_TOTAL];
__device__ int                g_counts[NQ_TOTAL];
__device__ double             g_sum;
__device__ unsigned int       g_done;

// ---- f32x2 packed FMA (sm_103a) -------------------------------------------
__device__ __forceinline__ unsigned long long ffma2(
    unsigned long long a, unsigned long long b, unsigned long long c) {
    unsigned long long d;
    asm("fma.rn.f32x2 %0, %1, %2, %3;" : "=l"(d) : "l"(a), "l"(b), "l"(c));
    return d;
}
__device__ __forceinline__ unsigned long long fdup2(float v) {
    unsigned long long r;
    asm("mov.b64 %0, {%1, %1};" : "=l"(r) : "f"(v));
    return r;
}
__device__ __forceinline__ float2 unpack2(unsigned long long v) {
    float2 r;
    asm("mov.b64 {%0, %1}, %2;" : "=f"(r.x), "=f"(r.y) : "l"(v));
    return r;
}

// ---------------------------------------------------------------------------
// Kernel 1: nearest-neighbor scan (R14 winner + finer grid for occupancy).
// score(q, m) = ||c_m||^2 - 2 <x_q, c_m>  (same argmin as full sq-dist)
// 4 queries/thread; SoA SMEM candidates; FFMA2 packed scores; fminf streams;
// (value, group-of-8) tracked; intra-group index recovered by bit-identical
// recompute over 2 quads. SEG=256 -> 2048 blocks -> 8 resident blocks/SM.
// Also zeroes counts / sum / ticket.
// ---------------------------------------------------------------------------
__global__ __launch_bounds__(TNN) void dacd_nn_kernel(
    const float* __restrict__ x, const float* __restrict__ gt)
{
    __shared__ __align__(16) float sc0[SEG];
    __shared__ __align__(16) float sc1[SEG];
    __shared__ __align__(16) float sc2[SEG];
    __shared__ __align__(16) float sw [SEG];

    const int blk = blockIdx.x;
    const int seg = blk & (NSEG - 1);            // bits [0,5)
    const int qc  = (blk >> 5) & (NQCHUNK - 1);  // bits [5,9)
    const int b   = (blk >> 9) & 1;
    const int dir = (blk >> 10) & 1;

    // Replace init kernel: each block zeroes its slice of counts.
    if (threadIdx.x < NQ_TOTAL / NN_BLOCKS)      // 16
        g_counts[blk * (NQ_TOTAL / NN_BLOCKS) + threadIdx.x] = 0;
    if (blk == 0 && threadIdx.x == 0) { g_sum = 0.0; g_done = 0u; }

    const float* qry = dir ? gt : x;
    const float* cnd = dir ? x : gt;

    const float* c0p = cnd + (b * 3 + 0) * NPTS + seg * SEG;
    const float* c1p = cnd + (b * 3 + 1) * NPTS + seg * SEG;
    const float* c2p = cnd + (b * 3 + 2) * NPTS + seg * SEG;

    for (int m = threadIdx.x; m < SEG; m += TNN) {
        float c0 = c0p[m], c1 = c1p[m], c2 = c2p[m];
        sc0[m] = c0; sc1[m] = c1; sc2[m] = c2;
        sw[m]  = fmaf(c0, c0, fmaf(c1, c1, c2 * c2));
    }
    __syncthreads();

    const float* qb = qry + b * 3 * NPTS;
    unsigned long long n0[QPT], n1[QPT], n2[QPT];
#pragma unroll
    for (int k = 0; k < QPT; k++) {
        int q = qc * QCHUNK + k * TNN + threadIdx.x;
        n0[k] = fdup2(-2.0f * qb[0 * NPTS + q]);
        n1[k] = fdup2(-2.0f * qb[1 * NPTS + q]);
        n2[k] = fdup2(-2.0f * qb[2 * NPTS + q]);
    }

    const float INF = __int_as_float(0x7f800000);
    float best[QPT];
    int   bg[QPT];
#pragma unroll
    for (int k = 0; k < QPT; k++) { best[k] = INF; bg[k] = 0; }

#pragma unroll 4
    for (int grp = 0; grp < SEG / GRP; grp++) {           // 32 groups
        float qm0[QPT], qm1[QPT];

#pragma unroll
        for (int sg = 0; sg < GRP / 4; sg++) {            // 2 quads
            const int m = grp * GRP + sg * 4;
            ulonglong2 C0 = *(const ulonglong2*)(sc0 + m);
            ulonglong2 C1 = *(const ulonglong2*)(sc1 + m);
            ulonglong2 C2 = *(const ulonglong2*)(sc2 + m);
            ulonglong2 W  = *(const ulonglong2*)(sw  + m);
#pragma unroll
            for (int k = 0; k < QPT; k++) {
                unsigned long long t0 = ffma2(n2[k], C2.x, W.x);
                t0 = ffma2(n1[k], C1.x, t0);
                t0 = ffma2(n0[k], C0.x, t0);
                unsigned long long t1 = ffma2(n2[k], C2.y, W.y);
                t1 = ffma2(n1[k], C1.y, t1);
                t1 = ffma2(n0[k], C0.y, t1);
                float2 p = unpack2(t0);
                float2 r = unpack2(t1);
                float qm = fminf(fminf(p.x, p.y), fminf(r.x, r.y));
                if (sg == 0) qm0[k] = qm; else qm1[k] = qm;
            }
        }
#pragma unroll
        for (int k = 0; k < QPT; k++) {
            float gm = fminf(qm0[k], qm1[k]);
            bool sel = gm < best[k];        // strict: earlier group wins ties
            bg[k]   = sel ? grp : bg[k];
            best[k] = fminf(best[k], gm);
        }
    }

    // Epilogue: rescan winning group (2 quads) bit-identically; FIRST
    // candidate (index order) achieving the min; plain coalesced store.
    unsigned long long* segbase =
        g_segkeys + seg * NQ_TOTAL + (dir * NB + b) * NPTS;
#pragma unroll 1
    for (int k = 0; k < QPT; k++) {
        int jj = -1;
        const int m0 = bg[k] * GRP;
#pragma unroll 1
        for (int sg = 0; sg < GRP / 4 && jj < 0; sg++) {  // <= 2 quads
            const int m = m0 + sg * 4;
            ulonglong2 C0 = *(const ulonglong2*)(sc0 + m);
            ulonglong2 C1 = *(const ulonglong2*)(sc1 + m);
            ulonglong2 C2 = *(const ulonglong2*)(sc2 + m);
            ulonglong2 W  = *(const ulonglong2*)(sw  + m);
            unsigned long long t0 = ffma2(n2[k], C2.x, W.x);
            t0 = ffma2(n1[k], C1.x, t0);
            t0 = ffma2(n0[k], C0.x, t0);
            unsigned long long t1 = ffma2(n2[k], C2.y, W.y);
            t1 = ffma2(n1[k], C1.y, t1);
            t1 = ffma2(n0[k], C0.y, t1);
            float2 p = unpack2(t0);
            float2 r = unpack2(t1);
            if      (p.x <= best[k]) jj = m + 0;
            else if (p.y <= best[k]) jj = m + 1;
            else if (r.x <= best[k]) jj = m + 2;
            else if (r.y <= best[k]) jj = m + 3;
        }
        unsigned u = __float_as_uint(best[k]);
        u ^= (u >> 31) ? 0xFFFFFFFFu : 0x80000000u;       // order-preserving
        int q = qc * QCHUNK + k * TNN + threadIdx.x;
        segbase[q] =
            ((unsigned long long)u << 32) | (unsigned)(seg * SEG + jj);
    }
}

// ---------------------------------------------------------------------------
// Kernel 2: per-query segment reduce (u64 min over 32 keys) + count histogram.
// ---------------------------------------------------------------------------
__global__ void dacd_reduce_count_kernel() {
    int i = blockIdx.x * blockDim.x + threadIdx.x;
    if (i >= NQ_TOTAL) return;
    unsigned long long best = g_segkeys[i];
#pragma unroll
    for (int s = 1; s < NSEG; s++) {
        unsigned long long k = g_segkeys[s * NQ_TOTAL + i];
        best = (k < best) ? k : best;
    }
    g_keys[i] = best;
    int base = i & ~(NPTS - 1);
    atomicAdd(&g_counts[base + (unsigned)(best & 0xFFFFFFFFu)], 1);
}

// ---------------------------------------------------------------------------
// Kernel 3: per-query loss + fused final reduction (ticket).
// term = 1 - exp(-10*dist)/(cnt+1e-6); dist = xx + score.
// ---------------------------------------------------------------------------
__global__ __launch_bounds__(TLOSS) void dacd_loss_kernel(
    const float* __restrict__ x, const float* __restrict__ gt,
    float* __restrict__ out)
{
    __shared__ double swarp[TLOSS / 32];

    const int i   = blockIdx.x * TLOSS + threadIdx.x;
    const int q   = i & (NPTS - 1);
    const int b   = (i >> 13) & 1;
    const int dir = (i >> 14) & 1;

    const float* qry = dir ? gt : x;

    unsigned long long key = g_keys[i];
    unsigned u = (unsigned)(key >> 32);
    unsigned orig = (u >> 31) ? (u ^ 0x80000000u) : ~u;
    float score = __uint_as_float(orig);

    float x0 = qry[(b * 3 + 0) * NPTS + q];
    float x1 = qry[(b * 3 + 1) * NPTS + q];
    float x2 = qry[(b * 3 + 2) * NPTS + q];
    float xx = fmaf(x0, x0, fmaf(x1, x1, x2 * x2));
    float dist = xx + score;

    int cnt = g_counts[(i & ~(NPTS - 1)) + (unsigned)(key & 0xFFFFFFFFu)];
    float w = 1.0f / ((float)cnt + 1e-6f);
    double v = (double)(1.0f - expf(-10.0f * dist) * w);

#pragma unroll
    for (int off = 16; off > 0; off >>= 1)
        v += __shfl_down_sync(0xFFFFFFFFu, v, off);

    int lane = threadIdx.x & 31, wid = threadIdx.x >> 5;
    if (lane == 0) swarp[wid] = v;
    __syncthreads();
    if (wid == 0) {
        v = (lane < TLOSS / 32) ? swarp[lane] : 0.0;
#pragma unroll
        for (int off = 4; off > 0; off >>= 1)
            v += __shfl_down_sync(0xFFFFFFFFu, v, off);
        if (lane == 0) {
            atomicAdd(&g_sum, v);
            __threadfence();
            unsigned t = atomicAdd(&g_done, 1u);
            if (t == LOSS_BLOCKS - 1)
                out[0] = (float)(g_sum / (double)(NPTS * 2 * NB));
        }
    }
}

extern "C" void kernel_launch(void* const* d_in, const int* in_sizes, int n_in,
                              void* d_out, int out_size) {
    const float* x  = (const float*)d_in[0];
    const float* gt = (const float*)d_in[1];
    float* out = (float*)d_out;

    dacd_nn_kernel<<<NN_BLOCKS, TNN>>>(x, gt);
    dacd_reduce_count_kernel<<<(NQ_TOTAL + 255) / 256, 256>>>();
    dacd_loss_kernel<<<LOSS_BLOCKS, TLOSS>>>(x, gt, out);
}

// round 16
// speedup vs baseline: 1.0345x; 1.0345x over previous
#include <cuda_runtime.h>
#include <math.h>
#include <stdint.h>

#define NPTS    8192
#define NB      2
#define TNN     128                        // threads per NN block
#define QPT     4                          // queries per thread
#define QCHUNK  (TNN * QPT)                // 512 queries per block
#define SEG     512                        // candidate segment
#define GRP     8                          // tracking-group size (2 quads)
#define NSEG    (NPTS / SEG)               // 16
#define NQCHUNK (NPTS / QCHUNK)            // 16
#define NQ_TOTAL (2 * NB * NPTS)           // 32768
#define NN_BLOCKS (2 * NB * NQCHUNK * NSEG)   // 1024
#define TLOSS   256
#define LOSS_BLOCKS (NQ_TOTAL / TLOSS)        // 128

// Scratch. g_segkeys[seg][global_q]: per-segment winner, plain stores (every
// slot rewritten each replay -> no init needed). Key packs
// (order-preserving score bits << 32 | candidate idx): u64 min == (min score,
// lowest idx), matching the reference argmin tie-break.
__device__ unsigned long long g_segkeys[NSEG * NQ_TOTAL];
__device__ unsigned long long g_keys[NQ_TOTAL];
__device__ int                g_counts[NQ_TOTAL];
__device__ double             g_sum;
__device__ unsigned int       g_done;

// ---- f32x2 packed FMA (sm_103a) -------------------------------------------
__device__ __forceinline__ unsigned long long ffma2(
    unsigned long long a, unsigned long long b, unsigned long long c) {
    unsigned long long d;
    asm("fma.rn.f32x2 %0, %1, %2, %3;" : "=l"(d) : "l"(a), "l"(b), "l"(c));
    return d;
}
__device__ __forceinline__ unsigned long long fdup2(float v) {
    unsigned long long r;
    asm("mov.b64 %0, {%1, %1};" : "=l"(r) : "f"(v));
    return r;
}
__device__ __forceinline__ float2 unpack2(unsigned long long v) {
    float2 r;
    asm("mov.b64 {%0, %1}, %2;" : "=f"(r.x), "=f"(r.y) : "l"(v));
    return r;
}

// ---------------------------------------------------------------------------
// Kernel 1: nearest-neighbor scan (R14 geometry + software-pipelined groups).
// score(q, m) = ||c_m||^2 - 2 <x_q, c_m>  (same argmin as full sq-dist)
// 4 queries/thread; SoA SMEM; per group-of-8: ALL 8 quad-vectors loaded into
// registers first, then 48 FFMA2 -> ptxas can overlap next group's LDS with
// current math (unroll 8, reg cap 85 via launch_bounds(128,6)).
// (value, group) tracked; index recovered by bit-identical 2-quad rescan.
// Also zeroes counts / sum / ticket.
// ---------------------------------------------------------------------------
__global__ __launch_bounds__(TNN, 6) void dacd_nn_kernel(
    const float* __restrict__ x, const float* __restrict__ gt)
{
    __shared__ __align__(16) float sc0[SEG];
    __shared__ __align__(16) float sc1[SEG];
    __shared__ __align__(16) float sc2[SEG];
    __shared__ __align__(16) float sw [SEG];

    const int blk = blockIdx.x;
    const int seg = blk & (NSEG - 1);            // bits [0,4)
    const int qc  = (blk >> 4) & (NQCHUNK - 1);  // bits [4,8)
    const int b   = (blk >> 8) & 1;
    const int dir = (blk >> 9) & 1;

    // Replace init kernel: each block zeroes its slice of counts.
    if (threadIdx.x < NQ_TOTAL / NN_BLOCKS)      // 32
        g_counts[blk * (NQ_TOTAL / NN_BLOCKS) + threadIdx.x] = 0;
    if (blk == 0 && threadIdx.x == 0) { g_sum = 0.0; g_done = 0u; }

    const float* qry = dir ? gt : x;
    const float* cnd = dir ? x : gt;

    const float* c0p = cnd + (b * 3 + 0) * NPTS + seg * SEG;
    const float* c1p = cnd + (b * 3 + 1) * NPTS + seg * SEG;
    const float* c2p = cnd + (b * 3 + 2) * NPTS + seg * SEG;

    for (int m = threadIdx.x; m < SEG; m += TNN) {
        float c0 = c0p[m], c1 = c1p[m], c2 = c2p[m];
        sc0[m] = c0; sc1[m] = c1; sc2[m] = c2;
        sw[m]  = fmaf(c0, c0, fmaf(c1, c1, c2 * c2));
    }
    __syncthreads();

    const float* qb = qry + b * 3 * NPTS;
    unsigned long long n0[QPT], n1[QPT], n2[QPT];
#pragma unroll
    for (int k = 0; k < QPT; k++) {
        int q = qc * QCHUNK + k * TNN + threadIdx.x;
        n0[k] = fdup2(-2.0f * qb[0 * NPTS + q]);
        n1[k] = fdup2(-2.0f * qb[1 * NPTS + q]);
        n2[k] = fdup2(-2.0f * qb[2 * NPTS + q]);
    }

    const float INF = __int_as_float(0x7f800000);
    float best[QPT];
    int   bg[QPT];
#pragma unroll
    for (int k = 0; k < QPT; k++) { best[k] = INF; bg[k] = 0; }

#pragma unroll 8
    for (int grp = 0; grp < SEG / GRP; grp++) {           // 64 groups
        const int m = grp * GRP;
        // Hoist: load BOTH quads' vectors before any math.
        ulonglong2 A0 = *(const ulonglong2*)(sc0 + m);
        ulonglong2 A1 = *(const ulonglong2*)(sc1 + m);
        ulonglong2 A2 = *(const ulonglong2*)(sc2 + m);
        ulonglong2 AW = *(const ulonglong2*)(sw  + m);
        ulonglong2 B0 = *(const ulonglong2*)(sc0 + m + 4);
        ulonglong2 B1 = *(const ulonglong2*)(sc1 + m + 4);
        ulonglong2 B2 = *(const ulonglong2*)(sc2 + m + 4);
        ulonglong2 BW = *(const ulonglong2*)(sw  + m + 4);

#pragma unroll
        for (int k = 0; k < QPT; k++) {
            unsigned long long t0 = ffma2(n2[k], A2.x, AW.x);
            t0 = ffma2(n1[k], A1.x, t0);
            t0 = ffma2(n0[k], A0.x, t0);
            unsigned long long t1 = ffma2(n2[k], A2.y, AW.y);
            t1 = ffma2(n1[k], A1.y, t1);
            t1 = ffma2(n0[k], A0.y, t1);
            unsigned long long u0 = ffma2(n2[k], B2.x, BW.x);
            u0 = ffma2(n1[k], B1.x, u0);
            u0 = ffma2(n0[k], B0.x, u0);
            unsigned long long u1 = ffma2(n2[k], B2.y, BW.y);
            u1 = ffma2(n1[k], B1.y, u1);
            u1 = ffma2(n0[k], B0.y, u1);

            float2 pa = unpack2(t0);
            float2 ra = unpack2(t1);
            float2 pb = unpack2(u0);
            float2 rb = unpack2(u1);
            float qa = fminf(fminf(pa.x, pa.y), fminf(ra.x, ra.y));
            float qbm = fminf(fminf(pb.x, pb.y), fminf(rb.x, rb.y));
            float gm = fminf(qa, qbm);

            bool sel = gm < best[k];        // strict: earlier group wins ties
            bg[k]   = sel ? grp : bg[k];
            best[k] = fminf(best[k], gm);
        }
    }

    // Epilogue: rescan winning group (2 quads) bit-identically; FIRST
    // candidate (index order) achieving the min; plain coalesced store.
    unsigned long long* segbase =
        g_segkeys + seg * NQ_TOTAL + (dir * NB + b) * NPTS;
#pragma unroll 1
    for (int k = 0; k < QPT; k++) {
        int jj = -1;
        const int m0 = bg[k] * GRP;
#pragma unroll 1
        for (int sg = 0; sg < GRP / 4 && jj < 0; sg++) {  // <= 2 quads
            const int m = m0 + sg * 4;
            ulonglong2 C0 = *(const ulonglong2*)(sc0 + m);
            ulonglong2 C1 = *(const ulonglong2*)(sc1 + m);
            ulonglong2 C2 = *(const ulonglong2*)(sc2 + m);
            ulonglong2 W  = *(const ulonglong2*)(sw  + m);
            unsigned long long t0 = ffma2(n2[k], C2.x, W.x);
            t0 = ffma2(n1[k], C1.x, t0);
            t0 = ffma2(n0[k], C0.x, t0);
            unsigned long long t1 = ffma2(n2[k], C2.y, W.y);
            t1 = ffma2(n1[k], C1.y, t1);
            t1 = ffma2(n0[k], C0.y, t1);
            float2 p = unpack2(t0);
            float2 r = unpack2(t1);
            if      (p.x <= best[k]) jj = m + 0;
            else if (p.y <= best[k]) jj = m + 1;
            else if (r.x <= best[k]) jj = m + 2;
            else if (r.y <= best[k]) jj = m + 3;
        }
        unsigned u = __float_as_uint(best[k]);
        u ^= (u >> 31) ? 0xFFFFFFFFu : 0x80000000u;       // order-preserving
        int q = qc * QCHUNK + k * TNN + threadIdx.x;
        segbase[q] =
            ((unsigned long long)u << 32) | (unsigned)(seg * SEG + jj);
    }
}

// ---------------------------------------------------------------------------
// Kernel 2: per-query segment reduce (u64 min over 16 keys) + count histogram.
// ---------------------------------------------------------------------------
__global__ void dacd_reduce_count_kernel() {
    int i = blockIdx.x * blockDim.x + threadIdx.x;
    if (i >= NQ_TOTAL) return;
    unsigned long long best = g_segkeys[i];
#pragma unroll
    for (int s = 1; s < NSEG; s++) {
        unsigned long long k = g_segkeys[s * NQ_TOTAL + i];
        best = (k < best) ? k : best;
    }
    g_keys[i] = best;
    int base = i & ~(NPTS - 1);
    atomicAdd(&g_counts[base + (unsigned)(best & 0xFFFFFFFFu)], 1);
}

// ---------------------------------------------------------------------------
// Kernel 3: per-query loss + fused final reduction (ticket).
// term = 1 - exp(-10*dist)/(cnt+1e-6); dist = xx + score.
// ---------------------------------------------------------------------------
__global__ __launch_bounds__(TLOSS) void dacd_loss_kernel(
    const float* __restrict__ x, const float* __restrict__ gt,
    float* __restrict__ out)
{
    __shared__ double swarp[TLOSS / 32];

    const int i   = blockIdx.x * TLOSS + threadIdx.x;
    const int q   = i & (NPTS - 1);
    const int b   = (i >> 13) & 1;
    const int dir = (i >> 14) & 1;

    const float* qry = dir ? gt : x;

    unsigned long long key = g_keys[i];
    unsigned u = (unsigned)(key >> 32);
    unsigned orig = (u >> 31) ? (u ^ 0x80000000u) : ~u;
    float score = __uint_as_float(orig);

    float x0 = qry[(b * 3 + 0) * NPTS + q];
    float x1 = qry[(b * 3 + 1) * NPTS + q];
    float x2 = qry[(b * 3 + 2) * NPTS + q];
    float xx = fmaf(x0, x0, fmaf(x1, x1, x2 * x2));
    float dist = xx + score;

    int cnt = g_counts[(i & ~(NPTS - 1)) + (unsigned)(key & 0xFFFFFFFFu)];
    float w = 1.0f / ((float)cnt + 1e-6f);
    double v = (double)(1.0f - expf(-10.0f * dist) * w);

#pragma unroll
    for (int off = 16; off > 0; off >>= 1)
        v += __shfl_down_sync(0xFFFFFFFFu, v, off);

    int lane = threadIdx.x & 31, wid = threadIdx.x >> 5;
    if (lane == 0) swarp[wid] = v;
    __syncthreads();
    if (wid == 0) {
        v = (lane < TLOSS / 32) ? swarp[lane] : 0.0;
#pragma unroll
        for (int off = 4; off > 0; off >>= 1)
            v += __shfl_down_sync(0xFFFFFFFFu, v, off);
        if (lane == 0) {
            atomicAdd(&g_sum, v);
            __threadfence();
            unsigned t = atomicAdd(&g_done, 1u);
            if (t == LOSS_BLOCKS - 1)
                out[0] = (float)(g_sum / (double)(NPTS * 2 * NB));
        }
    }
}

extern "C" void kernel_launch(void* const* d_in, const int* in_sizes, int n_in,
                              void* d_out, int out_size) {
    const float* x  = (const float*)d_in[0];
    const float* gt = (const float*)d_in[1];
    float* out = (float*)d_out;

    dacd_nn_kernel<<<NN_BLOCKS, TNN>>>(x, gt);
    dacd_reduce_count_kernel<<<(NQ_TOTAL + 255) / 256, 256>>>();
    dacd_loss_kernel<<<LOSS_BLOCKS, TLOSS>>>(x, gt, out);
}

// round 17
// speedup vs baseline: 1.0351x; 1.0006x over previous
#include <cuda_runtime.h>
#include <math.h>
#include <stdint.h>

#define NPTS    8192
#define NB      2
#define TNN     128                        // threads per NN block
#define QPT     4                          // queries per thread
#define QCHUNK  (TNN * QPT)                // 512 queries per block
#define SEG     512                        // candidate segment
#define GRP     8                          // tracking-group size (2 quads)
#define NSEG    (NPTS / SEG)               // 16
#define NQCHUNK (NPTS / QCHUNK)            // 16
#define NQ_TOTAL (2 * NB * NPTS)           // 32768
#define NN_BLOCKS (2 * NB * NQCHUNK * NSEG)   // 1024
#define TFIN    256
#define FIN_BLOCKS (NQ_TOTAL / TFIN)          // 128 (< 148 SMs: all resident)

// Scratch. g_segkeys[seg][global_q]: per-segment winner, plain stores (every
// slot rewritten each replay -> no init needed). Key packs
// (order-preserving score bits << 32 | candidate idx): u64 min == (min score,
// lowest idx), matching the reference argmin tie-break.
__device__ unsigned long long g_segkeys[NSEG * NQ_TOTAL];
__device__ int                g_counts[NQ_TOTAL];
__device__ double             g_sum;
__device__ unsigned int       g_done;
__device__ unsigned int       g_cnt_done;

// ---- f32x2 packed FMA (sm_103a) -------------------------------------------
__device__ __forceinline__ unsigned long long ffma2(
    unsigned long long a, unsigned long long b, unsigned long long c) {
    unsigned long long d;
    asm("fma.rn.f32x2 %0, %1, %2, %3;" : "=l"(d) : "l"(a), "l"(b), "l"(c));
    return d;
}
__device__ __forceinline__ unsigned long long fdup2(float v) {
    unsigned long long r;
    asm("mov.b64 %0, {%1, %1};" : "=l"(r) : "f"(v));
    return r;
}
__device__ __forceinline__ float2 unpack2(unsigned long long v) {
    float2 r;
    asm("mov.b64 {%0, %1}, %2;" : "=f"(r.x), "=f"(r.y) : "l"(v));
    return r;
}

// ---------------------------------------------------------------------------
// Kernel 1: nearest-neighbor scan (identical to R16 best: NN 47.3us).
// score(q, m) = ||c_m||^2 - 2 <x_q, c_m>  (same argmin as full sq-dist)
// 4 queries/thread; SoA SMEM; per group-of-8: ALL 8 quad-vectors loaded into
// registers first, then 48 FFMA2 (unroll 8, reg cap via launch_bounds(128,6)).
// (value, group) tracked; index recovered by bit-identical 2-quad rescan.
// Also zeroes counts / sum / tickets.
// ---------------------------------------------------------------------------
__global__ __launch_bounds__(TNN, 6) void dacd_nn_kernel(
    const float* __restrict__ x, const float* __restrict__ gt)
{
    __shared__ __align__(16) float sc0[SEG];
    __shared__ __align__(16) float sc1[SEG];
    __shared__ __align__(16) float sc2[SEG];
    __shared__ __align__(16) float sw [SEG];

    const int blk = blockIdx.x;
    const int seg = blk & (NSEG - 1);            // bits [0,4)
    const int qc  = (blk >> 4) & (NQCHUNK - 1);  // bits [4,8)
    const int b   = (blk >> 8) & 1;
    const int dir = (blk >> 9) & 1;

    // Replace init kernel: each block zeroes its slice of counts.
    if (threadIdx.x < NQ_TOTAL / NN_BLOCKS)      // 32
        g_counts[blk * (NQ_TOTAL / NN_BLOCKS) + threadIdx.x] = 0;
    if (blk == 0 && threadIdx.x == 0) {
        g_sum = 0.0; g_done = 0u; g_cnt_done = 0u;
    }

    const float* qry = dir ? gt : x;
    const float* cnd = dir ? x : gt;

    const float* c0p = cnd + (b * 3 + 0) * NPTS + seg * SEG;
    const float* c1p = cnd + (b * 3 + 1) * NPTS + seg * SEG;
    const float* c2p = cnd + (b * 3 + 2) * NPTS + seg * SEG;

    for (int m = threadIdx.x; m < SEG; m += TNN) {
        float c0 = c0p[m], c1 = c1p[m], c2 = c2p[m];
        sc0[m] = c0; sc1[m] = c1; sc2[m] = c2;
        sw[m]  = fmaf(c0, c0, fmaf(c1, c1, c2 * c2));
    }
    __syncthreads();

    const float* qb = qry + b * 3 * NPTS;
    unsigned long long n0[QPT], n1[QPT], n2[QPT];
#pragma unroll
    for (int k = 0; k < QPT; k++) {
        int q = qc * QCHUNK + k * TNN + threadIdx.x;
        n0[k] = fdup2(-2.0f * qb[0 * NPTS + q]);
        n1[k] = fdup2(-2.0f * qb[1 * NPTS + q]);
        n2[k] = fdup2(-2.0f * qb[2 * NPTS + q]);
    }

    const float INF = __int_as_float(0x7f800000);
    float best[QPT];
    int   bg[QPT];
#pragma unroll
    for (int k = 0; k < QPT; k++) { best[k] = INF; bg[k] = 0; }

#pragma unroll 8
    for (int grp = 0; grp < SEG / GRP; grp++) {           // 64 groups
        const int m = grp * GRP;
        // Hoist: load BOTH quads' vectors before any math.
        ulonglong2 A0 = *(const ulonglong2*)(sc0 + m);
        ulonglong2 A1 = *(const ulonglong2*)(sc1 + m);
        ulonglong2 A2 = *(const ulonglong2*)(sc2 + m);
        ulonglong2 AW = *(const ulonglong2*)(sw  + m);
        ulonglong2 B0 = *(const ulonglong2*)(sc0 + m + 4);
        ulonglong2 B1 = *(const ulonglong2*)(sc1 + m + 4);
        ulonglong2 B2 = *(const ulonglong2*)(sc2 + m + 4);
        ulonglong2 BW = *(const ulonglong2*)(sw  + m + 4);

#pragma unroll
        for (int k = 0; k < QPT; k++) {
            unsigned long long t0 = ffma2(n2[k], A2.x, AW.x);
            t0 = ffma2(n1[k], A1.x, t0);
            t0 = ffma2(n0[k], A0.x, t0);
            unsigned long long t1 = ffma2(n2[k], A2.y, AW.y);
            t1 = ffma2(n1[k], A1.y, t1);
            t1 = ffma2(n0[k], A0.y, t1);
            unsigned long long u0 = ffma2(n2[k], B2.x, BW.x);
            u0 = ffma2(n1[k], B1.x, u0);
            u0 = ffma2(n0[k], B0.x, u0);
            unsigned long long u1 = ffma2(n2[k], B2.y, BW.y);
            u1 = ffma2(n1[k], B1.y, u1);
            u1 = ffma2(n0[k], B0.y, u1);

            float2 pa = unpack2(t0);
            float2 ra = unpack2(t1);
            float2 pb = unpack2(u0);
            float2 rb = unpack2(u1);
            float qa  = fminf(fminf(pa.x, pa.y), fminf(ra.x, ra.y));
            float qbm = fminf(fminf(pb.x, pb.y), fminf(rb.x, rb.y));
            float gm  = fminf(qa, qbm);

            bool sel = gm < best[k];        // strict: earlier group wins ties
            bg[k]   = sel ? grp : bg[k];
            best[k] = fminf(best[k], gm);
        }
    }

    // Epilogue: rescan winning group (2 quads) bit-identically; FIRST
    // candidate (index order) achieving the min; plain coalesced store.
    unsigned long long* segbase =
        g_segkeys + seg * NQ_TOTAL + (dir * NB + b) * NPTS;
#pragma unroll 1
    for (int k = 0; k < QPT; k++) {
        int jj = -1;
        const int m0 = bg[k] * GRP;
#pragma unroll 1
        for (int sg = 0; sg < GRP / 4 && jj < 0; sg++) {  // <= 2 quads
            const int m = m0 + sg * 4;
            ulonglong2 C0 = *(const ulonglong2*)(sc0 + m);
            ulonglong2 C1 = *(const ulonglong2*)(sc1 + m);
            ulonglong2 C2 = *(const ulonglong2*)(sc2 + m);
            ulonglong2 W  = *(const ulonglong2*)(sw  + m);
            unsigned long long t0 = ffma2(n2[k], C2.x, W.x);
            t0 = ffma2(n1[k], C1.x, t0);
            t0 = ffma2(n0[k], C0.x, t0);
            unsigned long long t1 = ffma2(n2[k], C2.y, W.y);
            t1 = ffma2(n1[k], C1.y, t1);
            t1 = ffma2(n0[k], C0.y, t1);
            float2 p = unpack2(t0);
            float2 r = unpack2(t1);
            if      (p.x <= best[k]) jj = m + 0;
            else if (p.y <= best[k]) jj = m + 1;
            else if (r.x <= best[k]) jj = m + 2;
            else if (r.y <= best[k]) jj = m + 3;
        }
        unsigned u = __float_as_uint(best[k]);
        u ^= (u >> 31) ? 0xFFFFFFFFu : 0x80000000u;       // order-preserving
        int q = qc * QCHUNK + k * TNN + threadIdx.x;
        segbase[q] =
            ((unsigned long long)u << 32) | (unsigned)(seg * SEG + jj);
    }
}

// ---------------------------------------------------------------------------
// Kernel 2 (fused): segment reduce + count histogram + loss + final sum.
// 128 blocks (< 148 SMs -> all co-resident, spin barrier is deadlock-free).
// Phase 1: per-query u64 min over 16 segment keys (kept in REGISTERS),
//          count histogram via atomicAdd, ticket arrive.
// Spin:    wait for all 128 blocks' tickets (counts then complete).
// Phase 2: read count, term = 1 - exp(-10*dist)/(cnt+1e-6), deterministic
//          block reduce, fp64 atomic sum, last block writes fp32 scalar.
// ---------------------------------------------------------------------------
__global__ __launch_bounds__(TFIN) void dacd_finish_kernel(
    const float* __restrict__ x, const float* __restrict__ gt,
    float* __restrict__ out)
{
    __shared__ double swarp[TFIN / 32];

    const int i   = blockIdx.x * TFIN + threadIdx.x;
    const int q   = i & (NPTS - 1);
    const int b   = (i >> 13) & 1;
    const int dir = (i >> 14) & 1;

    // Phase 1: reduce segment keys (registers only).
    unsigned long long key = g_segkeys[i];
#pragma unroll
    for (int s = 1; s < NSEG; s++) {
        unsigned long long k2 = g_segkeys[s * NQ_TOTAL + i];
        key = (k2 < key) ? k2 : key;
    }
    const int base = i & ~(NPTS - 1);
    atomicAdd(&g_counts[base + (unsigned)(key & 0xFFFFFFFFu)], 1);

    __threadfence();
    __syncthreads();
    if (threadIdx.x == 0) {
        atomicAdd(&g_cnt_done, 1u);
        // Spin until all blocks' histograms are complete.
        while (*(volatile unsigned int*)&g_cnt_done < FIN_BLOCKS)
            __nanosleep(64);
    }
    __syncthreads();
    __threadfence();

    // Phase 2: loss.
    const float* qry = dir ? gt : x;
    unsigned u = (unsigned)(key >> 32);
    unsigned orig = (u >> 31) ? (u ^ 0x80000000u) : ~u;
    float score = __uint_as_float(orig);

    float x0 = qry[(b * 3 + 0) * NPTS + q];
    float x1 = qry[(b * 3 + 1) * NPTS + q];
    float x2 = qry[(b * 3 + 2) * NPTS + q];
    float xx = fmaf(x0, x0, fmaf(x1, x1, x2 * x2));
    float dist = xx + score;

    int cnt = g_counts[base + (unsigned)(key & 0xFFFFFFFFu)];
    float w = 1.0f / ((float)cnt + 1e-6f);
    double v = (double)(1.0f - expf(-10.0f * dist) * w);

#pragma unroll
    for (int off = 16; off > 0; off >>= 1)
        v += __shfl_down_sync(0xFFFFFFFFu, v, off);

    int lane = threadIdx.x & 31, wid = threadIdx.x >> 5;
    if (lane == 0) swarp[wid] = v;
    __syncthreads();
    if (wid == 0) {
        v = (lane < TFIN / 32) ? swarp[lane] : 0.0;
#pragma unroll
        for (int off = 4; off > 0; off >>= 1)
            v += __shfl_down_sync(0xFFFFFFFFu, v, off);
        if (lane == 0) {
            atomicAdd(&g_sum, v);
            __threadfence();
            unsigned t = atomicAdd(&g_done, 1u);
            if (t == FIN_BLOCKS - 1)
                out[0] = (float)(g_sum / (double)(NPTS * 2 * NB));
        }
    }
}

extern "C" void kernel_launch(void* const* d_in, const int* in_sizes, int n_in,
                              void* d_out, int out_size) {
    const float* x  = (const float*)d_in[0];
    const float* gt = (const float*)d_in[1];
    float* out = (float*)d_out;

    dacd_nn_kernel<<<NN_BLOCKS, TNN>>>(x, gt);
    dacd_finish_kernel<<<FIN_BLOCKS, TFIN>>>(x, gt, out);
}